// round 1
// baseline (speedup 1.0000x reference)
#include <cuda_runtime.h>

// Problem shape (fixed by dataset): grid [2,160,160,160,3] float32
#define BB 2
#define NX 160
#define NY 160
#define NZ 160

// Tiling
#define TY 12            // y rows per block (13 tiles * 12 = 156)
#define TZ 32            // z lanes per block (5 chunks * 32 covers 156 with last partial)
#define XSPLIT 4         // x segments for occupancy
#define XSTEPS 39        // 156 / XSPLIT
#define NTHREADS (TY*TZ) // 384

__device__ double g_be_sum;

__global__ void be_init_kernel() { g_be_sum = 0.0; }

__global__ __launch_bounds__(NTHREADS) void be_main_kernel(const float* __restrict__ g) {
    // 5-slice ring buffer: [slot][y (TY+4)][z (TZ+4)][comp]
    __shared__ float ring[5][TY + 4][TZ + 4][3];
    __shared__ float warp_part[NTHREADS / 32];

    const int tz  = threadIdx.x;            // 0..31
    const int ty  = threadIdx.y;            // 0..11
    const int tid = ty * TZ + tz;

    const int cz  = blockIdx.x;             // 0..4   z chunk
    const int cy  = blockIdx.y;             // 0..12  y tile
    const int b   = blockIdx.z / XSPLIT;    // batch
    const int seg = blockIdx.z % XSPLIT;    // x segment

    const int z0 = 2 + cz * TZ;
    const int y0 = 2 + cy * TY;
    const int xs = 2 + seg * XSTEPS;
    const int xe = xs + XSTEPS - 1;

    const int z = z0 + tz;
    const bool active = (z <= NZ - 3);      // z in [2,157]

    // ---- stage slice gx of the input into ring[slot] (coalesced: z,c fast) ----
    auto stage = [&](int gx, int slot) {
        const int gy0 = y0 - 2;             // >= 0
        const int gz0 = z0 - 2;             // >= 0
        #pragma unroll 2
        for (int i = tid; i < (TY + 4) * (TZ + 4) * 3; i += NTHREADS) {
            int c  = i % 3;
            int r  = i / 3;
            int rz = r % (TZ + 4);
            int ry = r / (TZ + 4);
            int gz = gz0 + rz;
            if (gz > NZ - 1) gz = NZ - 1;   // clamp; clamped values are never consumed
            ring[slot][ry][rz][c] =
                g[(((b * NX + gx) * NY) + (gy0 + ry)) * (NZ * 3) + gz * 3 + c];
        }
    };

    // Prologue: slices xs-2 .. xs+1 into slots (x % 5)
    for (int x = xs - 2; x <= xs + 1; ++x) stage(x, x % 5);

    const int ry = ty + 2;
    const int rz = tz + 2;
    #define SV(s, dy, dz, c) ring[(s)][ry + (dy)][rz + (dz)][(c)]

    float acc = 0.0f;
    for (int x = xs; x <= xe; ++x) {
        __syncthreads();                    // prior-step reads done before overwrite
        stage(x + 2, (x + 2) % 5);
        __syncthreads();                    // staging visible

        if (active) {
            const int sm2 = (x - 2) % 5, sm1 = (x - 1) % 5, s0 = x % 5;
            const int sp1 = (x + 1) % 5, sp2 = (x + 2) % 5;

            const float c0 = SV(s0, 0, 0, 0);
            const float c1 = SV(s0, 0, 0, 1);
            const float c2 = SV(s0, 0, 0, 2);

            // Pure second differences (raw; global 1/16 folded into epilogue)
            const float dxx0 = SV(sm2, 0, 0, 0) + SV(sp2, 0, 0, 0) - 2.0f * c0;
            const float dyy0 = SV(s0, -2, 0, 0) + SV(s0, 2, 0, 0) - 2.0f * c0;
            const float dyy1 = SV(s0, -2, 0, 1) + SV(s0, 2, 0, 1) - 2.0f * c1;
            const float dzz0 = SV(s0, 0, -2, 0) + SV(s0, 0, 2, 0) - 2.0f * c0;
            const float dzz1 = SV(s0, 0, -2, 1) + SV(s0, 0, 2, 1) - 2.0f * c1;
            const float dzz2 = SV(s0, 0, -2, 2) + SV(s0, 0, 2, 2) - 2.0f * c2;

            // Mixed second differences
            const float dxy0 = SV(sp1, 1, 0, 0) - SV(sp1, -1, 0, 0)
                             - SV(sm1, 1, 0, 0) + SV(sm1, -1, 0, 0);
            const float dxy1 = SV(sp1, 1, 0, 1) - SV(sp1, -1, 0, 1)
                             - SV(sm1, 1, 0, 1) + SV(sm1, -1, 0, 1);

            const float dxz0 = SV(sp1, 0, 1, 0) - SV(sp1, 0, -1, 0)
                             - SV(sm1, 0, 1, 0) + SV(sm1, 0, -1, 0);
            const float dxz1 = SV(sp1, 0, 1, 1) - SV(sp1, 0, -1, 1)
                             - SV(sm1, 0, 1, 1) + SV(sm1, 0, -1, 1);
            const float dxz2 = SV(sp1, 0, 1, 2) - SV(sp1, 0, -1, 2)
                             - SV(sm1, 0, 1, 2) + SV(sm1, 0, -1, 2);

            const float dyz0 = SV(s0, 1, 1, 0) - SV(s0, 1, -1, 0)
                             - SV(s0, -1, 1, 0) + SV(s0, -1, -1, 0);
            const float dyz1 = SV(s0, 1, 1, 1) - SV(s0, 1, -1, 1)
                             - SV(s0, -1, 1, 1) + SV(s0, -1, -1, 1);
            const float dyz2 = SV(s0, 1, 1, 2) - SV(s0, 1, -1, 2)
                             - SV(s0, -1, 1, 2) + SV(s0, -1, -1, 2);

            float v = dxx0 * dxx0;
            v = fmaf(2.0f * dyy0, dyy0, v);
            v = fmaf(2.0f * dzz0, dzz0, v);
            v = fmaf(3.0f * dxy0, dxy0, v);
            v = fmaf(3.0f * dxz0, dxz0, v);
            v = fmaf(4.0f * dyz0, dyz0, v);
            v = fmaf(dyy1, dyy1, v);
            v = fmaf(2.0f * dzz1, dzz1, v);
            v = fmaf(dxy1, dxy1, v);
            v = fmaf(2.0f * dxz1, dxz1, v);
            v = fmaf(3.0f * dyz1, dyz1, v);
            v = fmaf(dzz2, dzz2, v);
            v = fmaf(dxz2, dxz2, v);
            v = fmaf(dyz2, dyz2, v);
            acc += v;
        }
    }
    #undef SV

    // Block reduction
    float v = acc;
    #pragma unroll
    for (int o = 16; o > 0; o >>= 1) v += __shfl_down_sync(0xffffffffu, v, o);
    if ((tid & 31) == 0) warp_part[tid >> 5] = v;
    __syncthreads();
    if (tid == 0) {
        float s = 0.0f;
        #pragma unroll
        for (int w = 0; w < NTHREADS / 32; ++w) s += warp_part[w];
        atomicAdd(&g_be_sum, (double)s);
    }
}

__global__ void be_finalize_kernel(float* __restrict__ out) {
    const double n = (double)BB * 156.0 * 156.0 * 156.0 * 3.0;
    out[0] = (float)(g_be_sum / (16.0 * n));
}

extern "C" void kernel_launch(void* const* d_in, const int* in_sizes, int n_in,
                              void* d_out, int out_size) {
    const float* grid = (const float*)d_in[0];
    float* out = (float*)d_out;

    be_init_kernel<<<1, 1>>>();

    dim3 blk(TZ, TY, 1);
    dim3 grd(5, 13, BB * XSPLIT);   // z-chunks, y-tiles, batch*x-segments
    be_main_kernel<<<grd, blk>>>(grid);

    be_finalize_kernel<<<1, 1>>>(out);
}

// round 2
// speedup vs baseline: 1.6151x; 1.6151x over previous
#include <cuda_runtime.h>

// grid [2,160,160,160,3] float32
#define BB 2
#define NX 160
#define NY 160
#define NZ 160

#define TY 12
#define TZ 32
#define XSPLIT 6
#define XSTEPS 26              // 156 / XSPLIT
#define NTHREADS (TY*TZ)       // 384

#define RY (TY + 4)            // 16
#define RZ (TZ + 4)            // 36
#define SLICE (RY * RZ * 3)    // 1728 floats per staged slice
#define ROWW (NZ * 3)          // 480 floats per (b,x,y) row
#define NSTG 5                 // ceil(SLICE / NTHREADS) = 4.5 -> 5 (last predicated)

__device__ double g_be_sum;

__global__ void be_init_kernel() { g_be_sum = 0.0; }

__global__ __launch_bounds__(NTHREADS) void be_main_kernel(const float* __restrict__ g) {
    __shared__ float ring[5 * SLICE];
    __shared__ float warp_part[NTHREADS / 32];

    const int tz  = threadIdx.x;            // 0..31
    const int ty  = threadIdx.y;            // 0..11
    const int tid = ty * TZ + tz;

    const int cz  = blockIdx.x;             // 0..4
    const int cy  = blockIdx.y;             // 0..12
    const int b   = blockIdx.z / XSPLIT;
    const int seg = blockIdx.z % XSPLIT;

    const int z0 = 2 + cz * TZ;
    const int y0 = 2 + cy * TY;
    const int xs = 2 + seg * XSTEPS;

    const bool active = (z0 + tz) <= (NZ - 3);   // z in [2,157]

    // ---- x-independent staging map: smem index i = tid + k*NTHREADS ----
    int goff[NSTG];
    #pragma unroll
    for (int k = 0; k < NSTG; ++k) {
        int i = tid + k * NTHREADS;
        if (i < SLICE) {
            int ryi = i / (RZ * 3);
            int rzc = i - ryi * (RZ * 3);
            int zc  = (z0 - 2) * 3 + rzc;        // gz0*3 + rzc
            if (zc > ROWW - 1) zc = ROWW - 1;    // clamp; clamped never consumed
            goff[k] = ryi * ROWW + zc;
        } else {
            goff[k] = 0;
        }
    }

    const long long bbase = (long long)b * NX * NY * ROWW + (long long)(y0 - 2) * ROWW;
    #define GSLICE(gx) (g + bbase + (long long)(gx) * (NY * ROWW))

    // ---- prologue: stage slices xs-2 .. xs+1 ----
    for (int gx = xs - 2; gx <= xs + 1; ++gx) {
        const float* src = GSLICE(gx);
        float* dst = ring + (gx % 5) * SLICE;
        #pragma unroll
        for (int k = 0; k < NSTG; ++k) {
            int i = tid + k * NTHREADS;
            if (i < SLICE) dst[i] = src[goff[k]];
        }
    }

    // prefetch slice xs+2 into registers
    float pf[NSTG];
    {
        const float* src = GSLICE(xs + 2);
        #pragma unroll
        for (int k = 0; k < NSTG; ++k) {
            int i = tid + k * NTHREADS;
            if (i < SLICE) pf[k] = src[goff[k]];
        }
    }
    __syncthreads();

    // ---- center delay lines (registers) ----
    const int off0 = ((ty + 2) * RZ + (tz + 2)) * 3;
    // c0: slices x+2..x-2 (a..e, post-shift); c1,c2: only needed at slice x
    float c0a, c0b, c0c, c0d, c0e;
    float c1p2, c1p1, c1z, c2p2, c2p1, c2z;
    {
        const float* s;
        s = ring + ((xs + 1) % 5) * SLICE; c0a = s[off0]; c1p2 = s[off0 + 1]; c2p2 = s[off0 + 2];
        s = ring + ((xs    ) % 5) * SLICE; c0b = s[off0]; c1p1 = s[off0 + 1]; c2p1 = s[off0 + 2];
        s = ring + ((xs - 1) % 5) * SLICE; c0c = s[off0];
        s = ring + ((xs - 2) % 5) * SLICE; c0d = s[off0];
        c0e = 0.f; c1z = 0.f; c2z = 0.f;
    }

    int sm2 = (xs + 3) % 5, sm1 = (xs + 4) % 5, s0 = xs % 5;
    int sp1 = (xs + 1) % 5, sp2 = (xs + 2) % 5;

    #define Y (RZ * 3)
    #define Zw 3

    float acc = 0.0f;
    for (int step = 0; step < XSTEPS; ++step) {
        // STS prefetched slice x+2 (slot sp2 held x-3: not in anyone's read set)
        {
            float* dst = ring + sp2 * SLICE;
            #pragma unroll
            for (int k = 0; k < NSTG; ++k) {
                int i = tid + k * NTHREADS;
                if (i < SLICE) dst[i] = pf[k];
            }
        }
        // issue prefetch for slice x+3 (latency spans barrier + compute)
        {
            int gx = xs + step + 3;
            if (gx > NX - 1) gx = NX - 1;
            const float* src = GSLICE(gx);
            #pragma unroll
            for (int k = 0; k < NSTG; ++k) {
                int i = tid + k * NTHREADS;
                if (i < SLICE) pf[k] = src[goff[k]];
            }
        }
        __syncthreads();   // the ONLY barrier per step

        // pickup centers of freshly staged slice x+2, shift delay lines
        {
            const float* s = ring + sp2 * SLICE;
            float n0 = s[off0], n1 = s[off0 + 1], n2 = s[off0 + 2];
            c0e = c0d; c0d = c0c; c0c = c0b; c0b = c0a; c0a = n0;
            c1z = c1p1; c1p1 = c1p2; c1p2 = n1;
            c2z = c2p1; c2p1 = c2p2; c2p2 = n2;
        }

        if (active) {
            const float* Sm1 = ring + sm1 * SLICE;
            const float* S0  = ring + s0  * SLICE;
            const float* Sp1 = ring + sp1 * SLICE;

            // pure second differences (raw; /16 folded into epilogue)
            const float dxx0 = c0e + c0a - 2.0f * c0c;
            const float dyy0 = S0[off0 - 2*Y]      + S0[off0 + 2*Y]      - 2.0f * c0c;
            const float dyy1 = S0[off0 - 2*Y + 1]  + S0[off0 + 2*Y + 1]  - 2.0f * c1z;
            const float dzz0 = S0[off0 - 2*Zw]     + S0[off0 + 2*Zw]     - 2.0f * c0c;
            const float dzz1 = S0[off0 - 2*Zw + 1] + S0[off0 + 2*Zw + 1] - 2.0f * c1z;
            const float dzz2 = S0[off0 - 2*Zw + 2] + S0[off0 + 2*Zw + 2] - 2.0f * c2z;

            // mixed second differences
            const float dxy0 = Sp1[off0 + Y]     - Sp1[off0 - Y]     - Sm1[off0 + Y]     + Sm1[off0 - Y];
            const float dxy1 = Sp1[off0 + Y + 1] - Sp1[off0 - Y + 1] - Sm1[off0 + Y + 1] + Sm1[off0 - Y + 1];

            const float dxz0 = Sp1[off0 + Zw]     - Sp1[off0 - Zw]     - Sm1[off0 + Zw]     + Sm1[off0 - Zw];
            const float dxz1 = Sp1[off0 + Zw + 1] - Sp1[off0 - Zw + 1] - Sm1[off0 + Zw + 1] + Sm1[off0 - Zw + 1];
            const float dxz2 = Sp1[off0 + Zw + 2] - Sp1[off0 - Zw + 2] - Sm1[off0 + Zw + 2] + Sm1[off0 - Zw + 2];

            const float dyz0 = S0[off0 + Y + Zw]     - S0[off0 + Y - Zw]     - S0[off0 - Y + Zw]     + S0[off0 - Y - Zw];
            const float dyz1 = S0[off0 + Y + Zw + 1] - S0[off0 + Y - Zw + 1] - S0[off0 - Y + Zw + 1] + S0[off0 - Y - Zw + 1];
            const float dyz2 = S0[off0 + Y + Zw + 2] - S0[off0 + Y - Zw + 2] - S0[off0 - Y + Zw + 2] + S0[off0 - Y - Zw + 2];

            float v = dxx0 * dxx0;
            v = fmaf(2.0f * dyy0, dyy0, v);
            v = fmaf(2.0f * dzz0, dzz0, v);
            v = fmaf(3.0f * dxy0, dxy0, v);
            v = fmaf(3.0f * dxz0, dxz0, v);
            v = fmaf(4.0f * dyz0, dyz0, v);
            v = fmaf(dyy1, dyy1, v);
            v = fmaf(2.0f * dzz1, dzz1, v);
            v = fmaf(dxy1, dxy1, v);
            v = fmaf(2.0f * dxz1, dxz1, v);
            v = fmaf(3.0f * dyz1, dyz1, v);
            v = fmaf(dzz2, dzz2, v);
            v = fmaf(dxz2, dxz2, v);
            v = fmaf(dyz2, dyz2, v);
            acc += v;
        }

        // rotate ring slots: (x+3)%5 == old sm2
        int t = sm2; sm2 = sm1; sm1 = s0; s0 = sp1; sp1 = sp2; sp2 = t;
    }
    #undef Y
    #undef Zw
    #undef GSLICE

    // block reduction
    float v = acc;
    #pragma unroll
    for (int o = 16; o > 0; o >>= 1) v += __shfl_down_sync(0xffffffffu, v, o);
    if ((tid & 31) == 0) warp_part[tid >> 5] = v;
    __syncthreads();
    if (tid == 0) {
        float s = 0.0f;
        #pragma unroll
        for (int w = 0; w < NTHREADS / 32; ++w) s += warp_part[w];
        atomicAdd(&g_be_sum, (double)s);
    }
}

__global__ void be_finalize_kernel(float* __restrict__ out) {
    const double n = (double)BB * 156.0 * 156.0 * 156.0 * 3.0;
    out[0] = (float)(g_be_sum / (16.0 * n));
}

extern "C" void kernel_launch(void* const* d_in, const int* in_sizes, int n_in,
                              void* d_out, int out_size) {
    const float* grid = (const float*)d_in[0];
    float* out = (float*)d_out;

    be_init_kernel<<<1, 1>>>();

    dim3 blk(TZ, TY, 1);
    dim3 grd(5, 13, BB * XSPLIT);
    be_main_kernel<<<grd, blk>>>(grid);

    be_finalize_kernel<<<1, 1>>>(out);
}

// round 3
// speedup vs baseline: 1.7998x; 1.1144x over previous
#include <cuda_runtime.h>

// grid [2,160,160,160,3] float32
#define BB 2
#define NX 160
#define NY 160
#define NZ 160

#define TY 12
#define TZ 32
#define XSPLIT 6
#define XSTEPS 26               // 156 / XSPLIT
#define NTHREADS (TY*TZ)        // 384
#define NBLOCKS (5*13*BB*XSPLIT) // 780

#define RY (TY + 4)             // 16
#define RZ (TZ + 4)             // 36
#define SLICE (RY * RZ * 3)     // 1728 floats per staged slice
#define ROWW (NZ * 3)           // 480 floats per (b,x,y) row
#define NSTG 5                  // ceil(SLICE / NTHREADS)

__device__ double g_be_sum;
__device__ unsigned int g_be_cnt;

__device__ __forceinline__ void cp4(unsigned int dst_smem, const float* src) {
    asm volatile("cp.async.ca.shared.global [%0], [%1], 4;" :: "r"(dst_smem), "l"(src));
}
__device__ __forceinline__ void cp_commit() {
    asm volatile("cp.async.commit_group;" ::: "memory");
}
__device__ __forceinline__ void cp_wait0() {
    asm volatile("cp.async.wait_group 0;" ::: "memory");
}

__global__ __launch_bounds__(NTHREADS, 2)
void be_main_kernel(const float* __restrict__ g, float* __restrict__ out) {
    __shared__ float ring[4 * SLICE];
    __shared__ float warp_part[NTHREADS / 32];

    const int tz  = threadIdx.x;            // 0..31
    const int ty  = threadIdx.y;            // 0..11
    const int tid = ty * TZ + tz;

    const int cz  = blockIdx.x;             // 0..4
    const int cy  = blockIdx.y;             // 0..12
    const int b   = blockIdx.z / XSPLIT;
    const int seg = blockIdx.z % XSPLIT;

    const int z0 = 2 + cz * TZ;
    const int y0 = 2 + cy * TY;
    const int xs = 2 + seg * XSTEPS;

    const bool active = (z0 + tz) <= (NZ - 3);   // z in [2,157]

    // x-independent staging map: smem index i = tid + k*NTHREADS
    int goff[NSTG];
    #pragma unroll
    for (int k = 0; k < NSTG; ++k) {
        int i = tid + k * NTHREADS;
        if (i < SLICE) {
            int ryi = i / (RZ * 3);
            int rzc = i - ryi * (RZ * 3);
            int zc  = (z0 - 2) * 3 + rzc;
            if (zc > ROWW - 1) zc = ROWW - 1;    // clamp; clamped never consumed
            goff[k] = ryi * ROWW + zc;
        } else {
            goff[k] = 0;
        }
    }

    const long long bbase = (long long)b * NX * NY * ROWW + (long long)(y0 - 2) * ROWW;
    const unsigned int ring_s = (unsigned int)__cvta_generic_to_shared(ring);

    auto issue_slice = [&](int gx, int slot) {
        const float* src = g + bbase + (long long)gx * (NY * ROWW);
        unsigned int sbase = ring_s + (unsigned int)(slot * SLICE) * 4u;
        #pragma unroll
        for (int k = 0; k < NSTG; ++k) {
            int i = tid + k * NTHREADS;
            if (i < SLICE) cp4(sbase + (unsigned int)i * 4u, src + goff[k]);
        }
    };

    // ---- prologue: stage xs-2 .. xs+1 into the 4 ring slots ----
    for (int gx = xs - 2; gx <= xs + 1; ++gx) issue_slice(gx, gx & 3);
    cp_commit();
    cp_wait0();
    __syncthreads();

    const int off0 = ((ty + 2) * RZ + (tz + 2)) * 3;
    #define Y (RZ * 3)
    #define Zw 3

    int s0  = xs & 3;
    int sp1 = (xs + 1) & 3;
    int sp2 = (xs + 2) & 3;                 // == (xs-2)&3 : holds xs-2 now, reused for xs+2
    const int sm1p = 6 - s0 - sp1 - sp2;    // slot of xs-1

    // center delay lines
    float c0a, c0b, c0c, c0d, c0e;
    float c1p2, c1p1, c1z, c2p2, c2p1, c2z;
    // q delay lines for mixed x-derivatives: q(s) = S_s[+off] - S_s[-off]
    float q2_xy0, q2_xy1, q2_xz0, q2_xz1, q2_xz2;
    float q1_xy0, q1_xy1, q1_xz0, q1_xz1, q1_xz2;
    {
        const float* s;
        s = ring + sp1  * SLICE; c0a = s[off0]; c1p2 = s[off0 + 1]; c2p2 = s[off0 + 2];
        s = ring + s0   * SLICE; c0b = s[off0]; c1p1 = s[off0 + 1]; c2p1 = s[off0 + 2];
        q1_xy0 = s[off0 + Y]      - s[off0 - Y];
        q1_xy1 = s[off0 + Y + 1]  - s[off0 - Y + 1];
        q1_xz0 = s[off0 + Zw]     - s[off0 - Zw];
        q1_xz1 = s[off0 + Zw + 1] - s[off0 - Zw + 1];
        q1_xz2 = s[off0 + Zw + 2] - s[off0 - Zw + 2];
        s = ring + sm1p * SLICE; c0c = s[off0];
        q2_xy0 = s[off0 + Y]      - s[off0 - Y];
        q2_xy1 = s[off0 + Y + 1]  - s[off0 - Y + 1];
        q2_xz0 = s[off0 + Zw]     - s[off0 - Zw];
        q2_xz1 = s[off0 + Zw + 1] - s[off0 - Zw + 1];
        q2_xz2 = s[off0 + Zw + 2] - s[off0 - Zw + 2];
        s = ring + sp2  * SLICE; c0d = s[off0];   // slice xs-2
        c0e = 0.f; c1z = 0.f; c2z = 0.f;
    }
    __syncthreads();                 // prologue reads done before slot sp2 is overwritten

    // stage slice xs+2 into slot sp2
    issue_slice(xs + 2, sp2);
    cp_commit();

    float acc = 0.0f;
    for (int step = 0; step < XSTEPS; ++step) {
        cp_wait0();                  // slice x+2 landed
        __syncthreads();             // visible to all; prior-step reads done

        // stage slice x+3 into the free slot (held x-1, dead)
        const int snext = 6 - s0 - sp1 - sp2;
        {
            int gx = xs + step + 3;
            if (gx > NX - 1) gx = NX - 1;
            issue_slice(gx, snext);
            cp_commit();
        }

        // pickup centers of slice x+2, shift delay lines
        {
            const float* s = ring + sp2 * SLICE;
            float n0 = s[off0], n1 = s[off0 + 1], n2 = s[off0 + 2];
            c0e = c0d; c0d = c0c; c0c = c0b; c0b = c0a; c0a = n0;
            c1z = c1p1; c1p1 = c1p2; c1p2 = n1;
            c2z = c2p1; c2p1 = c2p2; c2p2 = n2;
        }

        // q taps from slice x+1
        const float* Sp1 = ring + sp1 * SLICE;
        const float qn_xy0 = Sp1[off0 + Y]      - Sp1[off0 - Y];
        const float qn_xy1 = Sp1[off0 + Y + 1]  - Sp1[off0 - Y + 1];
        const float qn_xz0 = Sp1[off0 + Zw]     - Sp1[off0 - Zw];
        const float qn_xz1 = Sp1[off0 + Zw + 1] - Sp1[off0 - Zw + 1];
        const float qn_xz2 = Sp1[off0 + Zw + 2] - Sp1[off0 - Zw + 2];

        if (active) {
            const float* S0 = ring + s0 * SLICE;

            const float dxx0 = c0e + c0a - 2.0f * c0c;
            const float dyy0 = S0[off0 - 2*Y]      + S0[off0 + 2*Y]      - 2.0f * c0c;
            const float dyy1 = S0[off0 - 2*Y + 1]  + S0[off0 + 2*Y + 1]  - 2.0f * c1z;
            const float dzz0 = S0[off0 - 2*Zw]     + S0[off0 + 2*Zw]     - 2.0f * c0c;
            const float dzz1 = S0[off0 - 2*Zw + 1] + S0[off0 + 2*Zw + 1] - 2.0f * c1z;
            const float dzz2 = S0[off0 - 2*Zw + 2] + S0[off0 + 2*Zw + 2] - 2.0f * c2z;

            const float dxy0 = qn_xy0 - q2_xy0;
            const float dxy1 = qn_xy1 - q2_xy1;
            const float dxz0 = qn_xz0 - q2_xz0;
            const float dxz1 = qn_xz1 - q2_xz1;
            const float dxz2 = qn_xz2 - q2_xz2;

            const float dyz0 = S0[off0 + Y + Zw]     - S0[off0 + Y - Zw]     - S0[off0 - Y + Zw]     + S0[off0 - Y - Zw];
            const float dyz1 = S0[off0 + Y + Zw + 1] - S0[off0 + Y - Zw + 1] - S0[off0 - Y + Zw + 1] + S0[off0 - Y - Zw + 1];
            const float dyz2 = S0[off0 + Y + Zw + 2] - S0[off0 + Y - Zw + 2] - S0[off0 - Y + Zw + 2] + S0[off0 - Y - Zw + 2];

            float v = dxx0 * dxx0;
            v = fmaf(2.0f * dyy0, dyy0, v);
            v = fmaf(2.0f * dzz0, dzz0, v);
            v = fmaf(3.0f * dxy0, dxy0, v);
            v = fmaf(3.0f * dxz0, dxz0, v);
            v = fmaf(4.0f * dyz0, dyz0, v);
            v = fmaf(dyy1, dyy1, v);
            v = fmaf(2.0f * dzz1, dzz1, v);
            v = fmaf(dxy1, dxy1, v);
            v = fmaf(2.0f * dxz1, dxz1, v);
            v = fmaf(3.0f * dyz1, dyz1, v);
            v = fmaf(dzz2, dzz2, v);
            v = fmaf(dxz2, dxz2, v);
            v = fmaf(dyz2, dyz2, v);
            acc += v;
        }

        // shift q delay lines
        q2_xy0 = q1_xy0; q2_xy1 = q1_xy1; q2_xz0 = q1_xz0; q2_xz1 = q1_xz1; q2_xz2 = q1_xz2;
        q1_xy0 = qn_xy0; q1_xy1 = qn_xy1; q1_xz0 = qn_xz0; q1_xz1 = qn_xz1; q1_xz2 = qn_xz2;

        // rotate ring slots
        s0 = sp1; sp1 = sp2; sp2 = snext;
    }
    #undef Y
    #undef Zw

    // block reduction
    float v = acc;
    #pragma unroll
    for (int o = 16; o > 0; o >>= 1) v += __shfl_down_sync(0xffffffffu, v, o);
    if ((tid & 31) == 0) warp_part[tid >> 5] = v;
    __syncthreads();
    if (tid == 0) {
        float s = 0.0f;
        #pragma unroll
        for (int w = 0; w < NTHREADS / 32; ++w) s += warp_part[w];
        atomicAdd(&g_be_sum, (double)s);
        __threadfence();
        unsigned int t = atomicAdd(&g_be_cnt, 1u);
        if (t == NBLOCKS - 1) {
            double total = atomicAdd(&g_be_sum, 0.0);   // ordered read of final sum
            const double n = (double)BB * 156.0 * 156.0 * 156.0 * 3.0;
            out[0] = (float)(total / (16.0 * n));
            g_be_cnt = 0;        // reset for next (graph-replayed) launch
            g_be_sum = 0.0;
        }
    }
}

extern "C" void kernel_launch(void* const* d_in, const int* in_sizes, int n_in,
                              void* d_out, int out_size) {
    const float* grid = (const float*)d_in[0];
    float* out = (float*)d_out;

    dim3 blk(TZ, TY, 1);
    dim3 grd(5, 13, BB * XSPLIT);
    be_main_kernel<<<grd, blk>>>(grid, out);
}

// round 4
// speedup vs baseline: 1.9809x; 1.1006x over previous
#include <cuda_runtime.h>

// grid [2,160,160,160,3] float32
#define BB 2
#define NX 160
#define NY 160
#define NZ 160

#define TY 12
#define TZ 32
#define XSPLIT 6
#define XSTEPS 26                // 156 / XSPLIT
#define NTHREADS (TY*TZ)         // 384
#define NBLOCKS (5*13*BB*XSPLIT) // 780

#define RY (TY + 4)              // 16
#define RZ (TZ + 4)              // 36
#define SLICE (RY * RZ * 3)      // 1728 floats per staged slice
#define ROWW (NZ * 3)            // 480 floats per (b,x,y) row
#define NSTG 5                   // ceil(SLICE / NTHREADS)

__device__ double g_be_sum;
__device__ unsigned int g_be_cnt;

__device__ __forceinline__ void cp4(unsigned int dst_smem, const float* src) {
    asm volatile("cp.async.ca.shared.global [%0], [%1], 4;" :: "r"(dst_smem), "l"(src));
}
__device__ __forceinline__ void cp_commit() {
    asm volatile("cp.async.commit_group;" ::: "memory");
}
__device__ __forceinline__ void cp_wait0() {
    asm volatile("cp.async.wait_group 0;" ::: "memory");
}
__device__ __forceinline__ void cp_wait1() {
    asm volatile("cp.async.wait_group 1;" ::: "memory");
}

__global__ __launch_bounds__(NTHREADS, 3)
void be_main_kernel(const float* __restrict__ g, float* __restrict__ out) {
    __shared__ float ring[5 * SLICE];
    __shared__ float warp_part[NTHREADS / 32];

    const int tz  = threadIdx.x;            // 0..31
    const int ty  = threadIdx.y;            // 0..11
    const int tid = ty * TZ + tz;

    const int cz  = blockIdx.x;             // 0..4
    const int cy  = blockIdx.y;             // 0..12
    const int b   = blockIdx.z / XSPLIT;
    const int seg = blockIdx.z % XSPLIT;

    const int z0 = 2 + cz * TZ;
    const int y0 = 2 + cy * TY;
    const int xs = 2 + seg * XSTEPS;

    const bool active = (z0 + tz) <= (NZ - 3);   // z in [2,157]

    // x-independent staging map: smem index i = tid + k*NTHREADS
    int goff[NSTG];
    #pragma unroll
    for (int k = 0; k < NSTG; ++k) {
        int i = tid + k * NTHREADS;
        if (i < SLICE) {
            int ryi = i / (RZ * 3);
            int rzc = i - ryi * (RZ * 3);
            int zc  = (z0 - 2) * 3 + rzc;
            if (zc > ROWW - 1) zc = ROWW - 1;    // clamp; clamped never consumed
            goff[k] = ryi * ROWW + zc;
        } else {
            goff[k] = 0;
        }
    }

    const long long bbase = (long long)b * NX * NY * ROWW + (long long)(y0 - 2) * ROWW;
    const unsigned int ring_s = (unsigned int)__cvta_generic_to_shared(ring);

    auto issue_slice = [&](int gx, int slot) {
        const float* src = g + bbase + (long long)gx * (NY * ROWW);
        unsigned int sbase = ring_s + (unsigned int)(slot * SLICE) * 4u;
        #pragma unroll
        for (int k = 0; k < NSTG; ++k) {
            int i = tid + k * NTHREADS;
            if (i < SLICE) cp4(sbase + (unsigned int)i * 4u, src + goff[k]);
        }
    };

    // ---- prologue: stage xs-2 .. xs+1 (slot = gx % 5), one group ----
    for (int gx = xs - 2; gx <= xs + 1; ++gx) issue_slice(gx, gx % 5);
    cp_commit();
    cp_wait0();
    __syncthreads();

    const int off0 = ((ty + 2) * RZ + (tz + 2)) * 3;
    #define Y (RZ * 3)
    #define Zw 3

    // ring slot cursors (slot(gx) = gx % 5)
    int sl_m1 = (xs + 4) % 5;   // xs-1
    int sl_0  = xs % 5;
    int sl_p1 = (xs + 1) % 5;
    int sl_p2 = (xs + 2) % 5;
    int sl_p3 = (xs + 3) % 5;   // == (xs-2)%5, overwritten after init reads

    // center delay lines
    float c0a, c0b, c0c, c0d, c0e;
    float c1p2, c1p1, c1z, c2p2, c2p1, c2z;
    // q delay lines for mixed x-derivatives: q(s) = S_s[+off] - S_s[-off]
    float q2_xy0, q2_xy1, q2_xz0, q2_xz1, q2_xz2;
    float q1_xy0, q1_xy1, q1_xz0, q1_xz1, q1_xz2;
    {
        const float* s;
        s = ring + sl_p1 * SLICE; c0a = s[off0]; c1p2 = s[off0 + 1]; c2p2 = s[off0 + 2];
        s = ring + sl_0  * SLICE; c0b = s[off0]; c1p1 = s[off0 + 1]; c2p1 = s[off0 + 2];
        q1_xy0 = s[off0 + Y]      - s[off0 - Y];
        q1_xy1 = s[off0 + Y + 1]  - s[off0 - Y + 1];
        q1_xz0 = s[off0 + Zw]     - s[off0 - Zw];
        q1_xz1 = s[off0 + Zw + 1] - s[off0 - Zw + 1];
        q1_xz2 = s[off0 + Zw + 2] - s[off0 - Zw + 2];
        s = ring + sl_m1 * SLICE; c0c = s[off0];
        q2_xy0 = s[off0 + Y]      - s[off0 - Y];
        q2_xy1 = s[off0 + Y + 1]  - s[off0 - Y + 1];
        q2_xz0 = s[off0 + Zw]     - s[off0 - Zw];
        q2_xz1 = s[off0 + Zw + 1] - s[off0 - Zw + 1];
        q2_xz2 = s[off0 + Zw + 2] - s[off0 - Zw + 2];
        s = ring + sl_p3 * SLICE; c0d = s[off0];   // slice xs-2 (slot reused for xs+3)
        c0e = 0.f; c1z = 0.f; c2z = 0.f;
    }
    __syncthreads();            // init reads done before slot reuse

    // launch the pipeline: xs+2 and xs+3 in flight (separate groups)
    issue_slice(xs + 2, sl_p2); cp_commit();
    issue_slice(xs + 3, sl_p3); cp_commit();

    float acc = 0.0f;
    for (int step = 0; step < XSTEPS; ++step) {
        cp_wait1();                 // x+2 landed (x+3 may still be in flight)
        __syncthreads();            // visible; prior-step reads of sl_m1 done

        // stage slice x+4 into the slot that held x-1 (dead)
        {
            int gx = xs + step + 4;
            if (gx > NX - 1) gx = NX - 1;
            issue_slice(gx, sl_m1);
            cp_commit();
        }

        // pickup centers of slice x+2, shift delay lines
        {
            const float* s = ring + sl_p2 * SLICE;
            float n0 = s[off0], n1 = s[off0 + 1], n2 = s[off0 + 2];
            c0e = c0d; c0d = c0c; c0c = c0b; c0b = c0a; c0a = n0;
            c1z = c1p1; c1p1 = c1p2; c1p2 = n1;
            c2z = c2p1; c2p1 = c2p2; c2p2 = n2;
        }

        // q taps from slice x+1
        const float* Sp1 = ring + sl_p1 * SLICE;
        const float qn_xy0 = Sp1[off0 + Y]      - Sp1[off0 - Y];
        const float qn_xy1 = Sp1[off0 + Y + 1]  - Sp1[off0 - Y + 1];
        const float qn_xz0 = Sp1[off0 + Zw]     - Sp1[off0 - Zw];
        const float qn_xz1 = Sp1[off0 + Zw + 1] - Sp1[off0 - Zw + 1];
        const float qn_xz2 = Sp1[off0 + Zw + 2] - Sp1[off0 - Zw + 2];

        if (active) {
            const float* S0 = ring + sl_0 * SLICE;

            const float dxx0 = c0e + c0a - 2.0f * c0c;
            const float dyy0 = S0[off0 - 2*Y]      + S0[off0 + 2*Y]      - 2.0f * c0c;
            const float dyy1 = S0[off0 - 2*Y + 1]  + S0[off0 + 2*Y + 1]  - 2.0f * c1z;
            const float dzz0 = S0[off0 - 2*Zw]     + S0[off0 + 2*Zw]     - 2.0f * c0c;
            const float dzz1 = S0[off0 - 2*Zw + 1] + S0[off0 + 2*Zw + 1] - 2.0f * c1z;
            const float dzz2 = S0[off0 - 2*Zw + 2] + S0[off0 + 2*Zw + 2] - 2.0f * c2z;

            const float dxy0 = qn_xy0 - q2_xy0;
            const float dxy1 = qn_xy1 - q2_xy1;
            const float dxz0 = qn_xz0 - q2_xz0;
            const float dxz1 = qn_xz1 - q2_xz1;
            const float dxz2 = qn_xz2 - q2_xz2;

            const float dyz0 = S0[off0 + Y + Zw]     - S0[off0 + Y - Zw]     - S0[off0 - Y + Zw]     + S0[off0 - Y - Zw];
            const float dyz1 = S0[off0 + Y + Zw + 1] - S0[off0 + Y - Zw + 1] - S0[off0 - Y + Zw + 1] + S0[off0 - Y - Zw + 1];
            const float dyz2 = S0[off0 + Y + Zw + 2] - S0[off0 + Y - Zw + 2] - S0[off0 - Y + Zw + 2] + S0[off0 - Y - Zw + 2];

            float v = dxx0 * dxx0;
            v = fmaf(2.0f * dyy0, dyy0, v);
            v = fmaf(2.0f * dzz0, dzz0, v);
            v = fmaf(3.0f * dxy0, dxy0, v);
            v = fmaf(3.0f * dxz0, dxz0, v);
            v = fmaf(4.0f * dyz0, dyz0, v);
            v = fmaf(dyy1, dyy1, v);
            v = fmaf(2.0f * dzz1, dzz1, v);
            v = fmaf(dxy1, dxy1, v);
            v = fmaf(2.0f * dxz1, dxz1, v);
            v = fmaf(3.0f * dyz1, dyz1, v);
            v = fmaf(dzz2, dzz2, v);
            v = fmaf(dxz2, dxz2, v);
            v = fmaf(dyz2, dyz2, v);
            acc += v;
        }

        // shift q delay lines
        q2_xy0 = q1_xy0; q2_xy1 = q1_xy1; q2_xz0 = q1_xz0; q2_xz1 = q1_xz1; q2_xz2 = q1_xz2;
        q1_xy0 = qn_xy0; q1_xy1 = qn_xy1; q1_xz0 = qn_xz0; q1_xz1 = qn_xz1; q1_xz2 = qn_xz2;

        // rotate ring cursors: new x-1 slot = old x slot, etc.
        int t = sl_m1;
        sl_m1 = sl_0; sl_0 = sl_p1; sl_p1 = sl_p2; sl_p2 = sl_p3; sl_p3 = t;
    }
    #undef Y
    #undef Zw

    // block reduction
    float v = acc;
    #pragma unroll
    for (int o = 16; o > 0; o >>= 1) v += __shfl_down_sync(0xffffffffu, v, o);
    if ((tid & 31) == 0) warp_part[tid >> 5] = v;
    __syncthreads();
    if (tid == 0) {
        float s = 0.0f;
        #pragma unroll
        for (int w = 0; w < NTHREADS / 32; ++w) s += warp_part[w];
        atomicAdd(&g_be_sum, (double)s);
        __threadfence();
        unsigned int t = atomicAdd(&g_be_cnt, 1u);
        if (t == NBLOCKS - 1) {
            double total = atomicAdd(&g_be_sum, 0.0);   // ordered read of final sum
            const double n = (double)BB * 156.0 * 156.0 * 156.0 * 3.0;
            out[0] = (float)(total / (16.0 * n));
            g_be_cnt = 0;        // reset for next (graph-replayed) launch
            g_be_sum = 0.0;
        }
    }
}

extern "C" void kernel_launch(void* const* d_in, const int* in_sizes, int n_in,
                              void* d_out, int out_size) {
    const float* grid = (const float*)d_in[0];
    float* out = (float*)d_out;

    dim3 blk(TZ, TY, 1);
    dim3 grd(5, 13, BB * XSPLIT);
    be_main_kernel<<<grd, blk>>>(grid, out);
}

// round 5
// speedup vs baseline: 2.4066x; 1.2149x over previous
#include <cuda_runtime.h>

// grid [2,160,160,160,3] float32
#define BB 2
#define NX 160
#define NY 160
#define NZ 160

#define TY 12
#define TZ 32
#define XSPLIT 6
#define XSTEPS 26                // 156 / XSPLIT
#define NTHREADS (TY*TZ)         // 384
#define NBLOCKS (5*13*BB*XSPLIT) // 780

#define RY (TY + 4)              // 16
#define RZ (TZ + 4)              // 36
#define SLICE (RY * RZ * 3)      // 1728 floats per staged slice
#define ROWW (NZ * 3)            // 480 floats per (b,x,y) row
#define CHUNKS (SLICE / 4)       // 432 16B chunks per slice
#define CPR (RZ * 3 / 4)         // 27 chunks per staged row

__device__ double g_be_sum;
__device__ unsigned int g_be_cnt;

__device__ __forceinline__ void cp16(unsigned int dst_smem, const float* src) {
    asm volatile("cp.async.cg.shared.global [%0], [%1], 16;" :: "r"(dst_smem), "l"(src));
}
__device__ __forceinline__ void cp_commit() {
    asm volatile("cp.async.commit_group;" ::: "memory");
}
__device__ __forceinline__ void cp_wait0() {
    asm volatile("cp.async.wait_group 0;" ::: "memory");
}
__device__ __forceinline__ void cp_wait1() {
    asm volatile("cp.async.wait_group 1;" ::: "memory");
}

__global__ __launch_bounds__(NTHREADS, 3)
void be_main_kernel(const float* __restrict__ g, float* __restrict__ out) {
    __shared__ float ring[5 * SLICE];
    __shared__ float warp_part[NTHREADS / 32];

    const int tz  = threadIdx.x;            // 0..31
    const int ty  = threadIdx.y;            // 0..11
    const int tid = ty * TZ + tz;

    const int cz  = blockIdx.x;             // 0..4
    const int cy  = blockIdx.y;             // 0..12
    const int b   = blockIdx.z / XSPLIT;
    const int seg = blockIdx.z % XSPLIT;

    const int z0 = 2 + cz * TZ;
    const int y0 = 2 + cy * TY;
    const int xs = 2 + seg * XSTEPS;

    const bool active = (z0 + tz) <= (NZ - 3);   // z in [2,157]

    // ---- 16B-chunk staging map (x-independent) ----
    // chunk j covers smem floats [4j, 4j+4); row = j/CPR, col16 = j%CPR
    // global float offset = row*ROWW + clamp(zbase3 + col16*4, <= ROWW-4)
    // (clamped chunks land in unused smem halo slack rz>=32, never read)
    const int zbase3 = (z0 - 2) * 3;
    int goffA, goffB;
    {
        int j = tid;
        int row = j / CPR, col = j - row * CPR;
        int o = zbase3 + col * 4;
        if (o > ROWW - 4) o = ROWW - 4;
        goffA = row * ROWW + o;
        j = tid + NTHREADS;
        row = j / CPR; col = j - row * CPR;
        o = zbase3 + col * 4;
        if (o > ROWW - 4) o = ROWW - 4;
        goffB = row * ROWW + o;                   // used only when tid < CHUNKS-NTHREADS
    }

    const long long bbase = (long long)b * NX * NY * ROWW + (long long)(y0 - 2) * ROWW;
    const unsigned int ring_s = (unsigned int)__cvta_generic_to_shared(ring);

    auto issue_slice = [&](int gx, int slot) {
        const float* src = g + bbase + (long long)gx * (NY * ROWW);
        unsigned int sbase = ring_s + (unsigned int)(slot * SLICE) * 4u;
        cp16(sbase + (unsigned int)tid * 16u, src + goffA);
        if (tid < CHUNKS - NTHREADS)
            cp16(sbase + (unsigned int)(tid + NTHREADS) * 16u, src + goffB);
    };

    // ---- prologue: stage xs-2 .. xs+1 (slot = gx % 5), one group ----
    for (int gx = xs - 2; gx <= xs + 1; ++gx) issue_slice(gx, gx % 5);
    cp_commit();
    cp_wait0();
    __syncthreads();

    const int off0 = ((ty + 2) * RZ + (tz + 2)) * 3;
    #define Y (RZ * 3)
    #define Zw 3

    // ring slot cursors (slot(gx) = gx % 5)
    int sl_m1 = (xs + 4) % 5;   // xs-1
    int sl_0  = xs % 5;
    int sl_p1 = (xs + 1) % 5;
    int sl_p2 = (xs + 2) % 5;
    int sl_p3 = (xs + 3) % 5;   // == (xs-2)%5, overwritten after init reads

    // center delay lines
    float c0a, c0b, c0c, c0d, c0e;
    float c1p2, c1p1, c1z, c2p2, c2p1, c2z;
    // q delay lines for mixed x-derivatives: q(s) = S_s[+off] - S_s[-off]
    float q2_xy0, q2_xy1, q2_xz0, q2_xz1, q2_xz2;
    float q1_xy0, q1_xy1, q1_xz0, q1_xz1, q1_xz2;
    {
        const float* s;
        s = ring + sl_p1 * SLICE; c0a = s[off0]; c1p2 = s[off0 + 1]; c2p2 = s[off0 + 2];
        s = ring + sl_0  * SLICE; c0b = s[off0]; c1p1 = s[off0 + 1]; c2p1 = s[off0 + 2];
        q1_xy0 = s[off0 + Y]      - s[off0 - Y];
        q1_xy1 = s[off0 + Y + 1]  - s[off0 - Y + 1];
        q1_xz0 = s[off0 + Zw]     - s[off0 - Zw];
        q1_xz1 = s[off0 + Zw + 1] - s[off0 - Zw + 1];
        q1_xz2 = s[off0 + Zw + 2] - s[off0 - Zw + 2];
        s = ring + sl_m1 * SLICE; c0c = s[off0];
        q2_xy0 = s[off0 + Y]      - s[off0 - Y];
        q2_xy1 = s[off0 + Y + 1]  - s[off0 - Y + 1];
        q2_xz0 = s[off0 + Zw]     - s[off0 - Zw];
        q2_xz1 = s[off0 + Zw + 1] - s[off0 - Zw + 1];
        q2_xz2 = s[off0 + Zw + 2] - s[off0 - Zw + 2];
        s = ring + sl_p3 * SLICE; c0d = s[off0];   // slice xs-2 (slot reused for xs+3)
        c0e = 0.f; c1z = 0.f; c2z = 0.f;
    }
    __syncthreads();            // init reads done before slot reuse

    // launch the pipeline: xs+2 and xs+3 in flight (separate groups)
    issue_slice(xs + 2, sl_p2); cp_commit();
    issue_slice(xs + 3, sl_p3); cp_commit();

    float acc = 0.0f;
    for (int step = 0; step < XSTEPS; ++step) {
        cp_wait1();                 // x+2 landed (x+3 may still be in flight)
        __syncthreads();            // visible; prior-step reads of sl_m1 done

        // stage slice x+4 into the slot that held x-1 (dead)
        {
            int gx = xs + step + 4;
            if (gx > NX - 1) gx = NX - 1;
            issue_slice(gx, sl_m1);
            cp_commit();
        }

        // pickup centers of slice x+2, shift delay lines
        {
            const float* s = ring + sl_p2 * SLICE;
            float n0 = s[off0], n1 = s[off0 + 1], n2 = s[off0 + 2];
            c0e = c0d; c0d = c0c; c0c = c0b; c0b = c0a; c0a = n0;
            c1z = c1p1; c1p1 = c1p2; c1p2 = n1;
            c2z = c2p1; c2p1 = c2p2; c2p2 = n2;
        }

        // q taps from slice x+1
        const float* Sp1 = ring + sl_p1 * SLICE;
        const float qn_xy0 = Sp1[off0 + Y]      - Sp1[off0 - Y];
        const float qn_xy1 = Sp1[off0 + Y + 1]  - Sp1[off0 - Y + 1];
        const float qn_xz0 = Sp1[off0 + Zw]     - Sp1[off0 - Zw];
        const float qn_xz1 = Sp1[off0 + Zw + 1] - Sp1[off0 - Zw + 1];
        const float qn_xz2 = Sp1[off0 + Zw + 2] - Sp1[off0 - Zw + 2];

        if (active) {
            const float* S0 = ring + sl_0 * SLICE;

            const float dxx0 = c0e + c0a - 2.0f * c0c;
            const float dyy0 = S0[off0 - 2*Y]      + S0[off0 + 2*Y]      - 2.0f * c0c;
            const float dyy1 = S0[off0 - 2*Y + 1]  + S0[off0 + 2*Y + 1]  - 2.0f * c1z;
            const float dzz0 = S0[off0 - 2*Zw]     + S0[off0 + 2*Zw]     - 2.0f * c0c;
            const float dzz1 = S0[off0 - 2*Zw + 1] + S0[off0 + 2*Zw + 1] - 2.0f * c1z;
            const float dzz2 = S0[off0 - 2*Zw + 2] + S0[off0 + 2*Zw + 2] - 2.0f * c2z;

            const float dxy0 = qn_xy0 - q2_xy0;
            const float dxy1 = qn_xy1 - q2_xy1;
            const float dxz0 = qn_xz0 - q2_xz0;
            const float dxz1 = qn_xz1 - q2_xz1;
            const float dxz2 = qn_xz2 - q2_xz2;

            const float dyz0 = S0[off0 + Y + Zw]     - S0[off0 + Y - Zw]     - S0[off0 - Y + Zw]     + S0[off0 - Y - Zw];
            const float dyz1 = S0[off0 + Y + Zw + 1] - S0[off0 + Y - Zw + 1] - S0[off0 - Y + Zw + 1] + S0[off0 - Y - Zw + 1];
            const float dyz2 = S0[off0 + Y + Zw + 2] - S0[off0 + Y - Zw + 2] - S0[off0 - Y + Zw + 2] + S0[off0 - Y - Zw + 2];

            float v = dxx0 * dxx0;
            v = fmaf(2.0f * dyy0, dyy0, v);
            v = fmaf(2.0f * dzz0, dzz0, v);
            v = fmaf(3.0f * dxy0, dxy0, v);
            v = fmaf(3.0f * dxz0, dxz0, v);
            v = fmaf(4.0f * dyz0, dyz0, v);
            v = fmaf(dyy1, dyy1, v);
            v = fmaf(2.0f * dzz1, dzz1, v);
            v = fmaf(dxy1, dxy1, v);
            v = fmaf(2.0f * dxz1, dxz1, v);
            v = fmaf(3.0f * dyz1, dyz1, v);
            v = fmaf(dzz2, dzz2, v);
            v = fmaf(dxz2, dxz2, v);
            v = fmaf(dyz2, dyz2, v);
            acc += v;
        }

        // shift q delay lines
        q2_xy0 = q1_xy0; q2_xy1 = q1_xy1; q2_xz0 = q1_xz0; q2_xz1 = q1_xz1; q2_xz2 = q1_xz2;
        q1_xy0 = qn_xy0; q1_xy1 = qn_xy1; q1_xz0 = qn_xz0; q1_xz1 = qn_xz1; q1_xz2 = qn_xz2;

        // rotate ring cursors
        int t = sl_m1;
        sl_m1 = sl_0; sl_0 = sl_p1; sl_p1 = sl_p2; sl_p2 = sl_p3; sl_p3 = t;
    }
    #undef Y
    #undef Zw

    // block reduction
    float v = acc;
    #pragma unroll
    for (int o = 16; o > 0; o >>= 1) v += __shfl_down_sync(0xffffffffu, v, o);
    if ((tid & 31) == 0) warp_part[tid >> 5] = v;
    __syncthreads();
    if (tid == 0) {
        float s = 0.0f;
        #pragma unroll
        for (int w = 0; w < NTHREADS / 32; ++w) s += warp_part[w];
        atomicAdd(&g_be_sum, (double)s);
        __threadfence();
        unsigned int t = atomicAdd(&g_be_cnt, 1u);
        if (t == NBLOCKS - 1) {
            double total = atomicAdd(&g_be_sum, 0.0);   // ordered read of final sum
            const double n = (double)BB * 156.0 * 156.0 * 156.0 * 3.0;
            out[0] = (float)(total / (16.0 * n));
            g_be_cnt = 0;        // reset for next (graph-replayed) launch
            g_be_sum = 0.0;
        }
    }
}

extern "C" void kernel_launch(void* const* d_in, const int* in_sizes, int n_in,
                              void* d_out, int out_size) {
    const float* grid = (const float*)d_in[0];
    float* out = (float*)d_out;

    dim3 blk(TZ, TY, 1);
    dim3 grd(5, 13, BB * XSPLIT);
    be_main_kernel<<<grd, blk>>>(grid, out);
}

// round 6
// speedup vs baseline: 2.6475x; 1.1001x over previous
#include <cuda_runtime.h>

// grid [2,160,160,160,3] float32
#define BB 2
#define NX 160
#define NY 160
#define NZ 160

#define TY 12
#define TZ 32
#define XSPLIT 6
#define XSTEPS 26                // 156 / XSPLIT
#define NTHREADS (TY*TZ)         // 384
#define NBLOCKS (5*13*BB*XSPLIT) // 780

#define RY (TY + 4)              // 16
#define RZ (TZ + 4)              // 36
#define SLICE (RY * RZ * 3)      // 1728 floats per staged slice
#define ROWW (NZ * 3)            // 480 floats per (b,x,y) row
#define CHUNKS (SLICE / 4)       // 432 16B chunks per slice
#define CPR (RZ * 3 / 4)         // 27 chunks per staged row

__device__ double g_be_sum;
__device__ unsigned int g_be_cnt;

__device__ __forceinline__ void cp16(unsigned int dst_smem, const float* src) {
    asm volatile("cp.async.cg.shared.global [%0], [%1], 16;" :: "r"(dst_smem), "l"(src));
}
__device__ __forceinline__ void cp_commit() {
    asm volatile("cp.async.commit_group;" ::: "memory");
}
__device__ __forceinline__ void cp_wait0() {
    asm volatile("cp.async.wait_group 0;" ::: "memory");
}
__device__ __forceinline__ void cp_wait1() {
    asm volatile("cp.async.wait_group 1;" ::: "memory");
}

__global__ __launch_bounds__(NTHREADS, 3)
void be_main_kernel(const float* __restrict__ g, float* __restrict__ out) {
    __shared__ float ring[5 * SLICE];
    __shared__ float warp_part[NTHREADS / 32];

    const int tz  = threadIdx.x;            // 0..31
    const int ty  = threadIdx.y;            // 0..11
    const int tid = ty * TZ + tz;

    const int cz  = blockIdx.x;             // 0..4
    const int cy  = blockIdx.y;             // 0..12
    const int b   = blockIdx.z / XSPLIT;
    const int seg = blockIdx.z % XSPLIT;

    const int z0 = 2 + cz * TZ;
    const int y0 = 2 + cy * TY;
    const int xs = 2 + seg * XSTEPS;

    const bool active = (z0 + tz) <= (NZ - 3);   // z in [2,157]

    // ---- 16B-chunk staging map (x-independent) ----
    const int zbase3 = (z0 - 2) * 3;
    int goffA, goffB;
    {
        int j = tid;
        int row = j / CPR, col = j - row * CPR;
        int o = zbase3 + col * 4;
        if (o > ROWW - 4) o = ROWW - 4;          // clamp: lands in unread halo slack
        goffA = row * ROWW + o;
        j = tid + NTHREADS;
        row = j / CPR; col = j - row * CPR;
        o = zbase3 + col * 4;
        if (o > ROWW - 4) o = ROWW - 4;
        goffB = row * ROWW + o;                   // used only when tid < CHUNKS-NTHREADS
    }

    const long long bbase = (long long)b * NX * NY * ROWW + (long long)(y0 - 2) * ROWW;
    const unsigned int ring_s = (unsigned int)__cvta_generic_to_shared(ring);

    auto issue_slice = [&](int gx, int slot) {
        const float* src = g + bbase + (long long)gx * (NY * ROWW);
        unsigned int sbase = ring_s + (unsigned int)(slot * SLICE) * 4u;
        cp16(sbase + (unsigned int)tid * 16u, src + goffA);
        if (tid < CHUNKS - NTHREADS)
            cp16(sbase + (unsigned int)(tid + NTHREADS) * 16u, src + goffB);
    };

    // ---- local slot numbering: slot(x) = (x - xs + 2) mod 5 ----
    // prologue: xs-2..xs+1 -> slots 0..3
    issue_slice(xs - 2, 0);
    issue_slice(xs - 1, 1);
    issue_slice(xs,     2);
    issue_slice(xs + 1, 3);
    cp_commit();
    cp_wait0();
    __syncthreads();

    const int off0 = ((ty + 2) * RZ + (tz + 2)) * 3;
    #define Y (RZ * 3)
    #define Zw 3

    // center delay lines
    float c0a, c0b, c0c, c0d, c0e;
    float c1p2, c1p1, c1z, c2p2, c2p1, c2z;
    // q delay lines for mixed x-derivatives
    float q2_xy0, q2_xy1, q2_xz0, q2_xz1, q2_xz2;
    float q1_xy0, q1_xy1, q1_xz0, q1_xz1, q1_xz2;
    {
        const float* s;
        s = ring + 3 * SLICE; c0a = s[off0]; c1p2 = s[off0 + 1]; c2p2 = s[off0 + 2]; // xs+1
        s = ring + 2 * SLICE; c0b = s[off0]; c1p1 = s[off0 + 1]; c2p1 = s[off0 + 2]; // xs
        q1_xy0 = s[off0 + Y]      - s[off0 - Y];
        q1_xy1 = s[off0 + Y + 1]  - s[off0 - Y + 1];
        q1_xz0 = s[off0 + Zw]     - s[off0 - Zw];
        q1_xz1 = s[off0 + Zw + 1] - s[off0 - Zw + 1];
        q1_xz2 = s[off0 + Zw + 2] - s[off0 - Zw + 2];
        s = ring + 1 * SLICE; c0c = s[off0];                                          // xs-1
        q2_xy0 = s[off0 + Y]      - s[off0 - Y];
        q2_xy1 = s[off0 + Y + 1]  - s[off0 - Y + 1];
        q2_xz0 = s[off0 + Zw]     - s[off0 - Zw];
        q2_xz1 = s[off0 + Zw + 1] - s[off0 - Zw + 1];
        q2_xz2 = s[off0 + Zw + 2] - s[off0 - Zw + 2];
        s = ring;             c0d = s[off0];                                          // xs-2 (slot 0)
        c0e = 0.f; c1z = 0.f; c2z = 0.f;
    }
    __syncthreads();            // init reads done before slot 0/4 reuse

    // pipeline: xs+2 -> slot 4, xs+3 -> slot 0 (two groups in flight)
    issue_slice(xs + 2, 4); cp_commit();
    issue_slice(xs + 3, 0); cp_commit();

    float acc = 0.0f;
    int gx4 = xs + 4;           // next slice to stage (x+4)

    // One stencil step with compile-time ring slots.
    #define DO_STEP(SM1i, S0i, SP1i, SP2i)                                        \
    {                                                                             \
        cp_wait1();                                                               \
        __syncthreads();                                                          \
        {                                                                         \
            int gxs = gx4 > (NX - 1) ? (NX - 1) : gx4;                            \
            issue_slice(gxs, (SM1i)); cp_commit(); ++gx4;                         \
        }                                                                         \
        {                                                                         \
            const float* sp = ring + (SP2i) * SLICE;                              \
            float n0 = sp[off0], n1 = sp[off0 + 1], n2 = sp[off0 + 2];            \
            c0e = c0d; c0d = c0c; c0c = c0b; c0b = c0a; c0a = n0;                 \
            c1z = c1p1; c1p1 = c1p2; c1p2 = n1;                                   \
            c2z = c2p1; c2p1 = c2p2; c2p2 = n2;                                   \
        }                                                                         \
        const float* Sp1 = ring + (SP1i) * SLICE;                                 \
        const float qn_xy0 = Sp1[off0 + Y]      - Sp1[off0 - Y];                  \
        const float qn_xy1 = Sp1[off0 + Y + 1]  - Sp1[off0 - Y + 1];              \
        const float qn_xz0 = Sp1[off0 + Zw]     - Sp1[off0 - Zw];                 \
        const float qn_xz1 = Sp1[off0 + Zw + 1] - Sp1[off0 - Zw + 1];             \
        const float qn_xz2 = Sp1[off0 + Zw + 2] - Sp1[off0 - Zw + 2];             \
        if (active) {                                                             \
            const float* S0 = ring + (S0i) * SLICE;                               \
            const float dxx0 = c0e + c0a - 2.0f * c0c;                            \
            const float dyy0 = S0[off0 - 2*Y]      + S0[off0 + 2*Y]      - 2.0f * c0c; \
            const float dyy1 = S0[off0 - 2*Y + 1]  + S0[off0 + 2*Y + 1]  - 2.0f * c1z; \
            const float dzz0 = S0[off0 - 2*Zw]     + S0[off0 + 2*Zw]     - 2.0f * c0c; \
            const float dzz1 = S0[off0 - 2*Zw + 1] + S0[off0 + 2*Zw + 1] - 2.0f * c1z; \
            const float dzz2 = S0[off0 - 2*Zw + 2] + S0[off0 + 2*Zw + 2] - 2.0f * c2z; \
            const float dxy0 = qn_xy0 - q2_xy0;                                   \
            const float dxy1 = qn_xy1 - q2_xy1;                                   \
            const float dxz0 = qn_xz0 - q2_xz0;                                   \
            const float dxz1 = qn_xz1 - q2_xz1;                                   \
            const float dxz2 = qn_xz2 - q2_xz2;                                   \
            const float dyz0 = S0[off0 + Y + Zw]     - S0[off0 + Y - Zw]     - S0[off0 - Y + Zw]     + S0[off0 - Y - Zw];         \
            const float dyz1 = S0[off0 + Y + Zw + 1] - S0[off0 + Y - Zw + 1] - S0[off0 - Y + Zw + 1] + S0[off0 - Y - Zw + 1];     \
            const float dyz2 = S0[off0 + Y + Zw + 2] - S0[off0 + Y - Zw + 2] - S0[off0 - Y + Zw + 2] + S0[off0 - Y - Zw + 2];     \
            float v = dxx0 * dxx0;                                                \
            v = fmaf(2.0f * dyy0, dyy0, v);                                       \
            v = fmaf(2.0f * dzz0, dzz0, v);                                       \
            v = fmaf(3.0f * dxy0, dxy0, v);                                       \
            v = fmaf(3.0f * dxz0, dxz0, v);                                       \
            v = fmaf(4.0f * dyz0, dyz0, v);                                       \
            v = fmaf(dyy1, dyy1, v);                                              \
            v = fmaf(2.0f * dzz1, dzz1, v);                                       \
            v = fmaf(dxy1, dxy1, v);                                              \
            v = fmaf(2.0f * dxz1, dxz1, v);                                       \
            v = fmaf(3.0f * dyz1, dyz1, v);                                       \
            v = fmaf(dzz2, dzz2, v);                                              \
            v = fmaf(dxz2, dxz2, v);                                              \
            v = fmaf(dyz2, dyz2, v);                                              \
            acc += v;                                                             \
        }                                                                         \
        q2_xy0 = q1_xy0; q2_xy1 = q1_xy1;                                         \
        q2_xz0 = q1_xz0; q2_xz1 = q1_xz1; q2_xz2 = q1_xz2;                        \
        q1_xy0 = qn_xy0; q1_xy1 = qn_xy1;                                         \
        q1_xz0 = qn_xz0; q1_xz1 = qn_xz1; q1_xz2 = qn_xz2;                        \
    }

    // 26 steps = 5 x 5 + 1 tail; slot pattern period 5 (all literals)
    #pragma unroll 1
    for (int it = 0; it < 5; ++it) {
        DO_STEP(1, 2, 3, 4);
        DO_STEP(2, 3, 4, 0);
        DO_STEP(3, 4, 0, 1);
        DO_STEP(4, 0, 1, 2);
        DO_STEP(0, 1, 2, 3);
    }
    DO_STEP(1, 2, 3, 4);        // step 25

    #undef DO_STEP
    #undef Y
    #undef Zw

    // block reduction
    float v = acc;
    #pragma unroll
    for (int o = 16; o > 0; o >>= 1) v += __shfl_down_sync(0xffffffffu, v, o);
    if ((tid & 31) == 0) warp_part[tid >> 5] = v;
    __syncthreads();
    if (tid == 0) {
        float s = 0.0f;
        #pragma unroll
        for (int w = 0; w < NTHREADS / 32; ++w) s += warp_part[w];
        atomicAdd(&g_be_sum, (double)s);
        __threadfence();
        unsigned int t = atomicAdd(&g_be_cnt, 1u);
        if (t == NBLOCKS - 1) {
            double total = atomicAdd(&g_be_sum, 0.0);   // ordered read of final sum
            const double n = (double)BB * 156.0 * 156.0 * 156.0 * 3.0;
            out[0] = (float)(total / (16.0 * n));
            g_be_cnt = 0;        // reset for next (graph-replayed) launch
            g_be_sum = 0.0;
        }
    }
}

extern "C" void kernel_launch(void* const* d_in, const int* in_sizes, int n_in,
                              void* d_out, int out_size) {
    const float* grid = (const float*)d_in[0];
    float* out = (float*)d_out;

    dim3 blk(TZ, TY, 1);
    dim3 grd(5, 13, BB * XSPLIT);
    be_main_kernel<<<grd, blk>>>(grid, out);
}